// round 7
// baseline (speedup 1.0000x reference)
#include <cuda_runtime.h>

#define NN 512
#define NB 16
#define MU 768

__device__ float2 g_A1[NB * NN * NN];   // row-FFT, only kx<=256 valid  [b][y][kx]
__device__ float2 g_A2[NB * NN * NN];   // half spectrum, kx<=256      [b][kx][ky]
__device__ float2 g_W[512];             // forward twiddles e^{-2pi i r/512}

__device__ __forceinline__ float2 cadd(float2 a, float2 b) { return make_float2(a.x + b.x, a.y + b.y); }
__device__ __forceinline__ float2 csub(float2 a, float2 b) { return make_float2(a.x - b.x, a.y - b.y); }
__device__ __forceinline__ float2 cmul(float2 a, float2 b) {
    return make_float2(a.x * b.x - a.y * b.y, a.x * b.y + a.y * b.x);
}

// bank-conflict-killing swizzle: XOR bits[4:6] into bits[1:3] (involution)
__device__ __forceinline__ int swz(int i) { return i ^ (((i >> 4) & 7) << 1); }

// per-FFT-unit barrier: 64 threads (2 warps), named barrier id in {1,2}
__device__ __forceinline__ void bar64(int id) {
    asm volatile("bar.sync %0, 64;" :: "r"(id) : "memory");
}

template <bool CONJ>
__device__ __forceinline__ void dft8(const float2 a[8], float2 b[8]) {
    const float C = 0.70710678118654752f;
    float2 u0 = cadd(a[0], a[4]), u1 = cadd(a[1], a[5]);
    float2 u2 = cadd(a[2], a[6]), u3 = cadd(a[3], a[7]);
    float2 v0 = csub(a[0], a[4]);
    float2 d1 = csub(a[1], a[5]);
    float2 d2 = csub(a[2], a[6]);
    float2 d3 = csub(a[3], a[7]);
    float2 v1, v2, v3;
    if (!CONJ) {
        v1 = make_float2(C * (d1.x + d1.y), C * (d1.y - d1.x));
        v2 = make_float2(d2.y, -d2.x);
        v3 = make_float2(C * (d3.y - d3.x), -C * (d3.x + d3.y));
    } else {
        v1 = make_float2(C * (d1.x - d1.y), C * (d1.x + d1.y));
        v2 = make_float2(-d2.y, d2.x);
        v3 = make_float2(-C * (d3.x + d3.y), C * (d3.x - d3.y));
    }
    {
        float2 x0 = cadd(u0, u2), x1 = cadd(u1, u3);
        float2 y0 = csub(u0, u2);
        float2 t = csub(u1, u3);
        float2 y1 = (!CONJ) ? make_float2(t.y, -t.x) : make_float2(-t.y, t.x);
        b[0] = cadd(x0, x1); b[4] = csub(x0, x1);
        b[2] = cadd(y0, y1); b[6] = csub(y0, y1);
    }
    {
        float2 x0 = cadd(v0, v2), x1 = cadd(v1, v3);
        float2 y0 = csub(v0, v2);
        float2 t = csub(v1, v3);
        float2 y1 = (!CONJ) ? make_float2(t.y, -t.x) : make_float2(-t.y, t.x);
        b[1] = cadd(x0, x1); b[5] = csub(x0, x1);
        b[3] = cadd(y0, y1); b[7] = csub(y0, y1);
    }
}

// In-place radix-8 Stockham stage: read to regs, bar, write back, bar.
template <bool CONJ, int M>
__device__ __forceinline__ void stage_ip(float2* buf, const float2* W, int p,
                                         int bid) {
    float2 a[8];
#pragma unroll
    for (int r = 0; r < 8; r++) a[r] = buf[swz(p + 64 * r)];
    bar64(bid);
    float2 b[8];
    dft8<CONJ>(a, b);
    if (M == 64) {
#pragma unroll
        for (int q = 0; q < 8; q++) buf[swz(p + 64 * q)] = b[q];
    } else {
        const int k = p & (M - 1);
        const int jm = p - k;
        float2 w1 = W[jm];
        if (CONJ) w1.y = -w1.y;
        float2 w2 = cmul(w1, w1);
        float2 w3 = cmul(w2, w1);
        float2 w4 = cmul(w2, w2);
        float2 w5 = cmul(w4, w1);
        float2 w6 = cmul(w4, w2);
        float2 w7 = cmul(w4, w3);
        const int base = 8 * jm + k;
        buf[swz(base)]         = b[0];
        buf[swz(base + M)]     = cmul(b[1], w1);
        buf[swz(base + 2 * M)] = cmul(b[2], w2);
        buf[swz(base + 3 * M)] = cmul(b[3], w3);
        buf[swz(base + 4 * M)] = cmul(b[4], w4);
        buf[swz(base + 5 * M)] = cmul(b[5], w5);
        buf[swz(base + 6 * M)] = cmul(b[6], w6);
        buf[swz(base + 7 * M)] = cmul(b[7], w7);
    }
    bar64(bid);
}

template <bool CONJ>
__device__ __forceinline__ void run_fft(float2* buf, const float2* W, int p,
                                        int bid) {
    stage_ip<CONJ, 1>(buf, W, p, bid);
    stage_ip<CONJ, 8>(buf, W, p, bid);
    stage_ip<CONJ, 64>(buf, W, p, bid);
}

__global__ void twiddle_init() {
    const int r = threadIdx.x;
    float s, c;
    sincosf(-6.283185307179586f * (float)r * (1.0f / 512.0f), &s, &c);
    g_W[r] = make_float2(c, s);
}

__device__ __forceinline__ void load_tw(float2* sW, int tid) {
    for (int r = tid; r < 512; r += 128) sW[r] = g_W[r];
}

// Stage A: forward FFT along x for PAIRS of real rows (Z = rowA + i*rowB).
// 128 threads = 2 FFT units = 4 rows per CTA. Store kx in [0,256] of A1.
__global__ __launch_bounds__(128, 10) void fft_rows(const float* __restrict__ img) {
    __shared__ float2 sF[2 * 512], sW[512];
    const int tid = threadIdx.x, f = tid >> 6, p = tid & 63;
    const int y0 = blockIdx.x * 4, b = blockIdx.y;   // 2 pairs = 4 rows per CTA
    load_tw(sW, tid);
    const float* src = img + ((size_t)b * NN + y0) * NN;
    for (int i = tid; i < 2 * 512; i += 128) {
        const int ff = i >> 9, x = i & 511;
        sF[ff * 512 + swz(x)] =
            make_float2(src[(2 * ff) * NN + x], src[(2 * ff + 1) * NN + x]);
    }
    __syncthreads();
    float2* buf = sF + f * 512;
    run_fft<false>(buf, sW, p, 1 + f);
    float2* dst = g_A1 + ((size_t)b * NN + y0) * NN;
    // Hermitian untangle: X[k] = (Z[k]+conj(Z[-k]))/2 ; Y[k] = -i(Z[k]-conj(Z[-k]))/2
#pragma unroll
    for (int k = p; k < 257; k += 64) {
        const float2 Zr = buf[swz(k)];
        const float2 Zs = buf[swz((512 - k) & 511)];
        const float2 X = make_float2(0.5f * (Zr.x + Zs.x), 0.5f * (Zr.y - Zs.y));
        const float2 Y = make_float2(0.5f * (Zr.y + Zs.y), 0.5f * (Zs.x - Zr.x));
        dst[(2 * f) * NN + k] = X;
        dst[(2 * f + 1) * NN + k] = Y;
    }
}

// Stage B: forward FFT along y for kx in [0,256]; store A2[kx][ky].
__global__ __launch_bounds__(128, 10) void fft_cols() {
    __shared__ float2 sF[2 * 512], sW[512];
    const int tid = threadIdx.x, f = tid >> 6, p = tid & 63;
    const int kx0 = blockIdx.x * 2, b = blockIdx.y;
    load_tw(sW, tid);
    const float2* src = g_A1 + (size_t)b * NN * NN;
    for (int i = tid; i < 2 * 512; i += 128) {
        const int c = i & 1, y = i >> 1;
        sF[c * 512 + swz(y)] = src[(size_t)y * NN + kx0 + c];
    }
    __syncthreads();
    float2* buf = sF + f * 512;
    run_fft<false>(buf, sW, p, 1 + f);
    const int kx = kx0 + f;
    if (kx <= 256) {
        float2* dst = g_A2 + ((size_t)b * NN + kx) * NN;
#pragma unroll
        for (int ky = p; ky < 512; ky += 64) dst[ky] = buf[swz(ky)];
    }
}

// Fetch slice[k] of line m from the half spectrum (conjugate mirror for kx>256).
//   m <  512: (kx,ky) = (k*m mod 512, k)
//   m >= 512: (kx,ky) = (k, 2k(m-512) mod 512)   [kx<=256 always for k<=256]
__device__ __forceinline__ float2 slice_elem(const float2* A2, int m, int k) {
    int kx, ky;
    if (m < NN) { kx = (k * m) & 511; ky = k; }
    else        { kx = k; ky = (2 * k * (m - NN)) & 511; }
    if (kx <= 256) return A2[(size_t)kx * NN + ky];
    const float2 v = A2[(size_t)(NN - kx) * NN + ((NN - ky) & 511)];
    return make_float2(v.x, -v.y);
}

// Stage C: slices are Hermitian: gather only k<=256, mirror-fill in smem.
// Two slices per inverse FFT (Z = s1 + i*s2). 2 units = 4 lines per CTA.
__global__ __launch_bounds__(128, 10) void gather_ifft(float* __restrict__ out) {
    __shared__ float2 sF[2 * 512], sW[512];
    const int tid = threadIdx.x, f = tid >> 6, p = tid & 63;
    const int base = blockIdx.x * 4, b = blockIdx.y;   // 2 pairs = 4 lines per CTA
    load_tw(sW, tid);
    const float2* A2 = g_A2 + (size_t)b * NN * NN;
    const int m1 = base + 2 * f, m2 = m1 + 1;
    float2* buf = sF + f * 512;
#pragma unroll
    for (int i = 0; i < 4; i++) {
        const int k = p + 64 * i;
        const float2 s1 = slice_elem(A2, m1, k);
        const float2 s2 = slice_elem(A2, m2, k);
        buf[swz(k)] = make_float2(s1.x - s2.y, s1.y + s2.x);
        if (k > 0)   // mirror: Z[512-k] = conj(s1) + i*conj(s2)
            buf[swz(512 - k)] = make_float2(s1.x + s2.y, s2.x - s1.y);
    }
    if (p == 0) {
        const float2 s1 = slice_elem(A2, m1, 256);
        const float2 s2 = slice_elem(A2, m2, 256);
        buf[swz(256)] = make_float2(s1.x - s2.y, s1.y + s2.x);
    }
    __syncthreads();
    run_fft<true>(buf, sW, p, 1 + f);
    const float SC = 8.6316745750242931e-5f;    // 1 / 512^1.5
    float2* o1 = (float2*)out + ((size_t)b * MU + m1) * NN;
    float2* o2 = (float2*)out + ((size_t)b * MU + m2) * NN;
#pragma unroll
    for (int s = p; s < 512; s += 64) {
        const float2 v = buf[swz(s)];
        o1[s] = make_float2(v.x * SC, 0.0f);
        o2[s] = make_float2(v.y * SC, 0.0f);
    }
}

extern "C" void kernel_launch(void* const* d_in, const int* in_sizes, int n_in,
                              void* d_out, int out_size) {
    const float* img = (const float*)d_in[0];
    float* out = (float*)d_out;

    twiddle_init<<<1, 512>>>();
    fft_rows<<<dim3(NN / 4, NB), 128>>>(img);
    fft_cols<<<dim3(129, NB), 128>>>();         // kx 0..257, guarded at 256
    gather_ifft<<<dim3(MU / 4, NB), 128>>>(out);
}